// round 2
// baseline (speedup 1.0000x reference)
#include <cuda_runtime.h>

#define NGROUPS 4
#define COUNT   96
#define BATCH   8
#define IMG     224
#define NPIX    (IMG * IMG)
#define ACC_N   (NGROUPS * BATCH * COUNT)

// Persistent accumulators: [group][batch][channel]
__device__ float g_cnt[ACC_N];
__device__ float g_sum[ACC_N];
__device__ int   g_max[ACC_N];   // float bits; all values >= 0 so int compare == float compare

__global__ void zero_acc_kernel() {
    int i = blockIdx.x * blockDim.x + threadIdx.x;
    if (i < ACC_N) {
        g_cnt[i] = 0.0f;
        g_sum[i] = 0.0f;
        g_max[i] = 0;      // == 0.0f
    }
}

// Tile: 56 (x) by 32 (y) output pixels. 224 threads: 7 x-groups of 8 pixels, 32 rows.
// 4 output channels per inner iteration: each shared-window load feeds 4*8*K FMAs.
template <int K>
__global__ __launch_bounds__(224, 4)
void conv_pool_kernel(const float* __restrict__ X,
                      const float* __restrict__ W,
                      const float* __restrict__ Bv,
                      int group)
{
    constexpr int P   = (K - 1) / 2;
    constexpr int TX  = 56;
    constexpr int TY  = 32;
    constexpr int SW  = TX + K - 1;
    constexpr int SH  = TY + K - 1;
    constexpr int SWP = SW + 1;          // pad stride (odd) to decorrelate banks

    __shared__ float s_in[3 * SH * SWP];

    const int bx  = blockIdx.x;          // 0..3  (x tiles)
    const int by  = blockIdx.y;          // 0..6  (y tiles)
    const int bz  = blockIdx.z;          // batch*3 + channel-block
    const int b   = bz / 3;
    const int cb  = bz % 3;              // 32 output channels per block
    const int gx0 = bx * TX;
    const int gy0 = by * TY;
    const int tid = threadIdx.x;

    // Cooperative halo load (zero padding outside image).
    const float* Xb = X + (size_t)b * 3 * NPIX;
    for (int idx = tid; idx < 3 * SH * SW; idx += 224) {
        int ci = idx / (SH * SW);
        int r  = idx % (SH * SW);
        int sy = r / SW;
        int sx = r % SW;
        int iy = gy0 - P + sy;
        int ix = gx0 - P + sx;
        float v = 0.0f;
        if (iy >= 0 && iy < IMG && ix >= 0 && ix < IMG)
            v = Xb[(ci * IMG + iy) * IMG + ix];
        s_in[(ci * SH + sy) * SWP + sx] = v;
    }
    __syncthreads();

    const int ty = tid / 7;              // 0..31
    const int xb = (tid % 7) * 8;        // 0,8,...,48

    const int acc_base = (group * BATCH + b) * COUNT;

    for (int cq = 0; cq < 8; ++cq) {     // 8 quads of output channels
        const int oc0 = cb * 32 + cq * 4;

        float acc[4][8];
        #pragma unroll
        for (int c = 0; c < 4; ++c)
            #pragma unroll
            for (int j = 0; j < 8; ++j) acc[c][j] = 0.0f;

        #pragma unroll
        for (int ci = 0; ci < 3; ++ci) {
            #pragma unroll
            for (int dy = 0; dy < K; ++dy) {
                const float* rp = &s_in[(ci * SH + ty + dy) * SWP + xb];
                float win[K + 7];
                #pragma unroll
                for (int j = 0; j < K + 7; ++j) win[j] = rp[j];

                const float* wp = &W[((oc0 * 3 + ci) * K + dy) * K];
                #pragma unroll
                for (int dx = 0; dx < K; ++dx) {
                    const float w0 = __ldg(wp + dx);
                    const float w1 = __ldg(wp + 3 * K * K + dx);
                    const float w2 = __ldg(wp + 6 * K * K + dx);
                    const float w3 = __ldg(wp + 9 * K * K + dx);
                    #pragma unroll
                    for (int j = 0; j < 8; ++j) {
                        acc[0][j] = fmaf(w0, win[dx + j], acc[0][j]);
                        acc[1][j] = fmaf(w1, win[dx + j], acc[1][j]);
                        acc[2][j] = fmaf(w2, win[dx + j], acc[2][j]);
                        acc[3][j] = fmaf(w3, win[dx + j], acc[3][j]);
                    }
                }
            }
        }

        #pragma unroll
        for (int c = 0; c < 4; ++c) {
            const int oc = oc0 + c;
            const float bias = __ldg(Bv + oc);
            float cnt = 0.0f, sum = 0.0f, mx = 0.0f;
            #pragma unroll
            for (int j = 0; j < 8; ++j) {
                float v = acc[c][j] + bias;
                if (v > 0.0f) { cnt += 1.0f; sum += v; mx = fmaxf(mx, v); }
            }
            #pragma unroll
            for (int off = 16; off > 0; off >>= 1) {
                cnt += __shfl_down_sync(0xffffffffu, cnt, off);
                sum += __shfl_down_sync(0xffffffffu, sum, off);
                mx  = fmaxf(mx, __shfl_down_sync(0xffffffffu, mx, off));
            }
            if ((tid & 31) == 0) {
                int idx = acc_base + oc;
                atomicAdd(&g_cnt[idx], cnt);
                atomicAdd(&g_sum[idx], sum);
                atomicMax(&g_max[idx], __float_as_int(mx));
            }
        }
    }
}

__global__ void finalize_kernel(float* __restrict__ out) {
    int i = blockIdx.x * blockDim.x + threadIdx.x;
    if (i >= ACC_N) return;
    int g = i / (BATCH * COUNT);
    int r = i % (BATCH * COUNT);
    int b = r / COUNT;
    int c = r % COUNT;

    float cnt = g_cnt[i];
    float sum = g_sum[i];
    float mx  = __int_as_float(g_max[i]);

    float ppv = cnt * (1.0f / (float)NPIX);
    float mpv = (cnt > 0.0f) ? (sum / cnt) : 0.0f;

    float* o = out + (size_t)b * (NGROUPS * 3 * COUNT) + g * (3 * COUNT);
    o[c]             = ppv;
    o[COUNT + c]     = mpv;
    o[2 * COUNT + c] = mx;
}

extern "C" void kernel_launch(void* const* d_in, const int* in_sizes, int n_in,
                              void* d_out, int out_size)
{
    const float* X  = (const float*)d_in[0];
    const float* w3 = (const float*)d_in[1];
    const float* b3 = (const float*)d_in[2];
    const float* w5 = (const float*)d_in[3];
    const float* b5 = (const float*)d_in[4];
    const float* w7 = (const float*)d_in[5];
    const float* b7 = (const float*)d_in[6];
    const float* w9 = (const float*)d_in[7];
    const float* b9 = (const float*)d_in[8];
    float* out = (float*)d_out;

    zero_acc_kernel<<<(ACC_N + 255) / 256, 256>>>();

    dim3 grid(4, 7, BATCH * 3);   // 4 x-tiles, 7 y-tiles, batch * channel-blocks
    conv_pool_kernel<3><<<grid, 224>>>(X, w3, b3, 0);
    conv_pool_kernel<5><<<grid, 224>>>(X, w5, b5, 1);
    conv_pool_kernel<7><<<grid, 224>>>(X, w7, b7, 2);
    conv_pool_kernel<9><<<grid, 224>>>(X, w9, b9, 3);

    finalize_kernel<<<(ACC_N + 255) / 256, 256>>>(out);
}

// round 3
// speedup vs baseline: 1.3800x; 1.3800x over previous
#include <cuda_runtime.h>

#define NGROUPS 4
#define COUNT   96
#define BATCH   8
#define IMG     224
#define NPIX    (IMG * IMG)
#define ACC_N   (NGROUPS * BATCH * COUNT)

// Persistent accumulators: [group][batch][channel]
__device__ float g_cnt[ACC_N];
__device__ float g_sum[ACC_N];
__device__ int   g_max[ACC_N];   // float bits; all values >= 0 so int compare == float compare

__global__ void zero_acc_kernel() {
    int i = blockIdx.x * blockDim.x + threadIdx.x;
    if (i < ACC_N) {
        g_cnt[i] = 0.0f;
        g_sum[i] = 0.0f;
        g_max[i] = 0;      // == 0.0f
    }
}

// Tile: 56 (x) by 32 (y) output pixels. 224 threads: 7 x-groups of 8 pixels, 32 rows.
// 2 output channels per inner iteration; window loaded as 4x float4 (LDS.128).
template <int K>
__global__ __launch_bounds__(224)
void conv_pool_kernel(const float* __restrict__ X,
                      const float* __restrict__ W,
                      const float* __restrict__ Bv,
                      int group)
{
    constexpr int P   = (K - 1) / 2;
    constexpr int TX  = 56;
    constexpr int TY  = 32;
    constexpr int SW  = TX + K - 1;      // 58..64
    constexpr int SH  = TY + K - 1;
    constexpr int SWP = 68;              // row stride: 16B-aligned, 68 mod 32 = 4 (bank decorrelation),
                                         // and >= 64 so win[16] reads at xb=48 stay in-row.

    __shared__ float s_in[3 * SH * SWP];

    const int bx  = blockIdx.x;          // 0..3  (x tiles)
    const int by  = blockIdx.y;          // 0..6  (y tiles)
    const int bz  = blockIdx.z;          // batch*3 + channel-block
    const int b   = bz / 3;
    const int cb  = bz % 3;              // 32 output channels per block
    const int gx0 = bx * TX;
    const int gy0 = by * TY;
    const int tid = threadIdx.x;

    // Cooperative halo load (zero padding outside image).
    const float* Xb = X + (size_t)b * 3 * NPIX;
    for (int idx = tid; idx < 3 * SH * SW; idx += 224) {
        int ci = idx / (SH * SW);
        int r  = idx % (SH * SW);
        int sy = r / SW;
        int sx = r % SW;
        int iy = gy0 - P + sy;
        int ix = gx0 - P + sx;
        float v = 0.0f;
        if (iy >= 0 && iy < IMG && ix >= 0 && ix < IMG)
            v = Xb[(ci * IMG + iy) * IMG + ix];
        s_in[(ci * SH + sy) * SWP + sx] = v;
    }
    __syncthreads();

    const int ty = tid / 7;              // 0..31
    const int xb = (tid % 7) * 8;        // 0,8,...,48  (multiple of 8 -> 16B aligned base)

    const int acc_base = (group * BATCH + b) * COUNT;

    for (int cpair = 0; cpair < 16; ++cpair) {
        const int oca = cb * 32 + cpair * 2;
        const int ocb = oca + 1;

        float accA[8], accB[8];
        #pragma unroll
        for (int j = 0; j < 8; ++j) { accA[j] = 0.0f; accB[j] = 0.0f; }

        #pragma unroll
        for (int ci = 0; ci < 3; ++ci) {
            #pragma unroll
            for (int dy = 0; dy < K; ++dy) {
                // ---- 4x LDS.128 window load (16 floats; only K+7 used) ----
                const float4* rp4 = (const float4*)&s_in[(ci * SH + ty + dy) * SWP + xb];
                float4 w4[4];
                #pragma unroll
                for (int q = 0; q < 4; ++q) w4[q] = rp4[q];
                const float* win = (const float*)w4;

                // ---- batched weight loads for both channels of this row ----
                const float* wpA = &W[((oca * 3 + ci) * K + dy) * K];
                const float* wpB = &W[((ocb * 3 + ci) * K + dy) * K];
                float wA[K], wB[K];
                #pragma unroll
                for (int dx = 0; dx < K; ++dx) {
                    wA[dx] = __ldg(wpA + dx);
                    wB[dx] = __ldg(wpB + dx);
                }

                #pragma unroll
                for (int dx = 0; dx < K; ++dx) {
                    #pragma unroll
                    for (int j = 0; j < 8; ++j) {
                        accA[j] = fmaf(wA[dx], win[dx + j], accA[j]);
                        accB[j] = fmaf(wB[dx], win[dx + j], accB[j]);
                    }
                }
            }
        }

        const float biasA = __ldg(Bv + oca);
        const float biasB = __ldg(Bv + ocb);

        // ---- channel A: branchless bias + relu + local stats ----
        {
            float cnt = 0.0f, sum = 0.0f, mx = 0.0f;
            #pragma unroll
            for (int j = 0; j < 8; ++j) {
                float v = accA[j] + biasA;
                float r = fmaxf(v, 0.0f);
                cnt += (v > 0.0f) ? 1.0f : 0.0f;
                sum += r;
                mx   = fmaxf(mx, r);
            }
            #pragma unroll
            for (int off = 16; off > 0; off >>= 1) {
                cnt += __shfl_down_sync(0xffffffffu, cnt, off);
                sum += __shfl_down_sync(0xffffffffu, sum, off);
                mx  = fmaxf(mx, __shfl_down_sync(0xffffffffu, mx, off));
            }
            if ((tid & 31) == 0) {
                int idx = acc_base + oca;
                atomicAdd(&g_cnt[idx], cnt);
                atomicAdd(&g_sum[idx], sum);
                atomicMax(&g_max[idx], __float_as_int(mx));
            }
        }
        // ---- channel B ----
        {
            float cnt = 0.0f, sum = 0.0f, mx = 0.0f;
            #pragma unroll
            for (int j = 0; j < 8; ++j) {
                float v = accB[j] + biasB;
                float r = fmaxf(v, 0.0f);
                cnt += (v > 0.0f) ? 1.0f : 0.0f;
                sum += r;
                mx   = fmaxf(mx, r);
            }
            #pragma unroll
            for (int off = 16; off > 0; off >>= 1) {
                cnt += __shfl_down_sync(0xffffffffu, cnt, off);
                sum += __shfl_down_sync(0xffffffffu, sum, off);
                mx  = fmaxf(mx, __shfl_down_sync(0xffffffffu, mx, off));
            }
            if ((tid & 31) == 0) {
                int idx = acc_base + ocb;
                atomicAdd(&g_cnt[idx], cnt);
                atomicAdd(&g_sum[idx], sum);
                atomicMax(&g_max[idx], __float_as_int(mx));
            }
        }
    }
}

__global__ void finalize_kernel(float* __restrict__ out) {
    int i = blockIdx.x * blockDim.x + threadIdx.x;
    if (i >= ACC_N) return;
    int g = i / (BATCH * COUNT);
    int r = i % (BATCH * COUNT);
    int b = r / COUNT;
    int c = r % COUNT;

    float cnt = g_cnt[i];
    float sum = g_sum[i];
    float mx  = __int_as_float(g_max[i]);

    float ppv = cnt * (1.0f / (float)NPIX);
    float mpv = (cnt > 0.0f) ? (sum / cnt) : 0.0f;

    float* o = out + (size_t)b * (NGROUPS * 3 * COUNT) + g * (3 * COUNT);
    o[c]             = ppv;
    o[COUNT + c]     = mpv;
    o[2 * COUNT + c] = mx;
}

extern "C" void kernel_launch(void* const* d_in, const int* in_sizes, int n_in,
                              void* d_out, int out_size)
{
    const float* X  = (const float*)d_in[0];
    const float* w3 = (const float*)d_in[1];
    const float* b3 = (const float*)d_in[2];
    const float* w5 = (const float*)d_in[3];
    const float* b5 = (const float*)d_in[4];
    const float* w7 = (const float*)d_in[5];
    const float* b7 = (const float*)d_in[6];
    const float* w9 = (const float*)d_in[7];
    const float* b9 = (const float*)d_in[8];
    float* out = (float*)d_out;

    zero_acc_kernel<<<(ACC_N + 255) / 256, 256>>>();

    dim3 grid(4, 7, BATCH * 3);   // 4 x-tiles, 7 y-tiles, batch * channel-blocks
    conv_pool_kernel<3><<<grid, 224>>>(X, w3, b3, 0);
    conv_pool_kernel<5><<<grid, 224>>>(X, w5, b5, 1);
    conv_pool_kernel<7><<<grid, 224>>>(X, w7, b7, 2);
    conv_pool_kernel<9><<<grid, 224>>>(X, w9, b9, 3);

    finalize_kernel<<<(ACC_N + 255) / 256, 256>>>(out);
}

// round 4
// speedup vs baseline: 1.5234x; 1.1040x over previous
#include <cuda_runtime.h>

#define NGROUPS 4
#define COUNT   96
#define BATCH   8
#define IMG     224
#define NPIX    (IMG * IMG)
#define ACC_N   (NGROUPS * BATCH * COUNT)

#define KMAX    9
#define WROW    12   // padded dx stride (floats), 16B-aligned rows

// Persistent accumulators: [group][batch][channel]
__device__ float g_cnt[ACC_N];
__device__ float g_sum[ACC_N];
__device__ int   g_max[ACC_N];   // float bits; post-ReLU values >= 0 so int cmp == float cmp

// Padded, aligned weights: [group][oc][ci][dy][WROW]
__device__ float g_wpad[NGROUPS * COUNT * 3 * KMAX * WROW];

__global__ void zero_acc_kernel() {
    int i = blockIdx.x * blockDim.x + threadIdx.x;
    if (i < ACC_N) { g_cnt[i] = 0.0f; g_sum[i] = 0.0f; g_max[i] = 0; }
}

__global__ void pack_weights_kernel(const float* __restrict__ w3,
                                    const float* __restrict__ w5,
                                    const float* __restrict__ w7,
                                    const float* __restrict__ w9)
{
    int i = blockIdx.x * blockDim.x + threadIdx.x;          // over [g][oc][ci][dy][WROW]
    const int TOT = NGROUPS * COUNT * 3 * KMAX * WROW;
    if (i >= TOT) return;
    int dx = i % WROW;
    int t  = i / WROW;
    int dy = t % KMAX;  t /= KMAX;
    int ci = t % 3;     t /= 3;
    int oc = t % COUNT;
    int g  = t / COUNT;
    const int ks[4] = {3, 5, 7, 9};
    int K = ks[g];
    float v = 0.0f;
    if (dx < K && dy < K) {
        const float* W = (g == 0) ? w3 : (g == 1) ? w5 : (g == 2) ? w7 : w9;
        v = W[((oc * 3 + ci) * K + dy) * K + dx];
    }
    g_wpad[i] = v;
}

// Tile: 32x32 outputs, 128 threads (4 x-groups of 8 px, 32 rows).
// Warp mapping ty=tid/4, xb=(tid%4)*8 with row stride 68 -> conflict-free LDS.128.
template <int K>
__global__ __launch_bounds__(128)
void conv_pool_kernel(const float* __restrict__ X,
                      const float* __restrict__ Bv,
                      int group)
{
    constexpr int P   = (K - 1) / 2;
    constexpr int TX  = 32;
    constexpr int TY  = 32;
    constexpr int SW  = TX + K - 1;      // <= 40
    constexpr int SH  = TY + K - 1;      // <= 40
    constexpr int SWP = 68;              // stride: mod 32 == 4 (bank rotate), mod 4 == 0 (16B align)
    constexpr int NWV = (K + 3) / 4;     // float4s per weight row

    __shared__ float s_in[3 * SH * SWP];

    const int bx  = blockIdx.x;          // 0..6
    const int by  = blockIdx.y;          // 0..6
    const int bz  = blockIdx.z;          // batch*3 + channel-block
    const int b   = bz / 3;
    const int cb  = bz % 3;              // 32 output channels per block
    const int gx0 = bx * TX;
    const int gy0 = by * TY;
    const int tid = threadIdx.x;

    // Cooperative halo load (zero padding outside image).
    const float* Xb = X + (size_t)b * 3 * NPIX;
    for (int idx = tid; idx < 3 * SH * SW; idx += 128) {
        int ci = idx / (SH * SW);
        int r  = idx % (SH * SW);
        int sy = r / SW;
        int sx = r % SW;
        int iy = gy0 - P + sy;
        int ix = gx0 - P + sx;
        float v = 0.0f;
        if (iy >= 0 && iy < IMG && ix >= 0 && ix < IMG)
            v = Xb[(ci * IMG + iy) * IMG + ix];
        s_in[(ci * SH + sy) * SWP + sx] = v;
    }
    __syncthreads();

    const int ty = tid / 4;              // 0..31
    const int xb = (tid % 4) * 8;        // 0,8,16,24

    const int acc_base = (group * BATCH + b) * COUNT;
    const float* Wp = g_wpad + (size_t)(group * COUNT) * 3 * KMAX * WROW;

    for (int cpair = 0; cpair < 16; ++cpair) {
        const int oca = cb * 32 + cpair * 2;
        const int ocb = oca + 1;

        float accA[8], accB[8];
        #pragma unroll
        for (int j = 0; j < 8; ++j) { accA[j] = 0.0f; accB[j] = 0.0f; }

        #pragma unroll
        for (int ci = 0; ci < 3; ++ci) {
            #pragma unroll
            for (int dy = 0; dy < K; ++dy) {
                // ---- window: 4x LDS.128, conflict-free ----
                const float4* rp4 = (const float4*)&s_in[(ci * SH + ty + dy) * SWP + xb];
                float4 w4[4];
                #pragma unroll
                for (int q = 0; q < 4; ++q) w4[q] = rp4[q];
                const float* win = (const float*)w4;

                // ---- weights: NWV x LDG.128 per channel (uniform, aligned) ----
                const float4* wra = (const float4*)&Wp[((oca * 3 + ci) * KMAX + dy) * WROW];
                const float4* wrb = (const float4*)&Wp[((ocb * 3 + ci) * KMAX + dy) * WROW];
                float4 qa[NWV], qb[NWV];
                #pragma unroll
                for (int q = 0; q < NWV; ++q) { qa[q] = wra[q]; qb[q] = wrb[q]; }
                const float* wA = (const float*)qa;
                const float* wB = (const float*)qb;

                #pragma unroll
                for (int dx = 0; dx < K; ++dx) {
                    #pragma unroll
                    for (int j = 0; j < 8; ++j) {
                        accA[j] = fmaf(wA[dx], win[dx + j], accA[j]);
                        accB[j] = fmaf(wB[dx], win[dx + j], accB[j]);
                    }
                }
            }
        }

        const float biasA = __ldg(Bv + oca);
        const float biasB = __ldg(Bv + ocb);

        // ---- channel A: branchless bias + relu + stats + warp reduce ----
        {
            float cnt = 0.0f, sum = 0.0f, mx = 0.0f;
            #pragma unroll
            for (int j = 0; j < 8; ++j) {
                float v = accA[j] + biasA;
                float r = fmaxf(v, 0.0f);
                cnt += (v > 0.0f) ? 1.0f : 0.0f;
                sum += r;
                mx   = fmaxf(mx, r);
            }
            #pragma unroll
            for (int off = 16; off > 0; off >>= 1) {
                cnt += __shfl_down_sync(0xffffffffu, cnt, off);
                sum += __shfl_down_sync(0xffffffffu, sum, off);
                mx  = fmaxf(mx, __shfl_down_sync(0xffffffffu, mx, off));
            }
            if ((tid & 31) == 0) {
                int idx = acc_base + oca;
                atomicAdd(&g_cnt[idx], cnt);
                atomicAdd(&g_sum[idx], sum);
                atomicMax(&g_max[idx], __float_as_int(mx));
            }
        }
        // ---- channel B ----
        {
            float cnt = 0.0f, sum = 0.0f, mx = 0.0f;
            #pragma unroll
            for (int j = 0; j < 8; ++j) {
                float v = accB[j] + biasB;
                float r = fmaxf(v, 0.0f);
                cnt += (v > 0.0f) ? 1.0f : 0.0f;
                sum += r;
                mx   = fmaxf(mx, r);
            }
            #pragma unroll
            for (int off = 16; off > 0; off >>= 1) {
                cnt += __shfl_down_sync(0xffffffffu, cnt, off);
                sum += __shfl_down_sync(0xffffffffu, sum, off);
                mx  = fmaxf(mx, __shfl_down_sync(0xffffffffu, mx, off));
            }
            if ((tid & 31) == 0) {
                int idx = acc_base + ocb;
                atomicAdd(&g_cnt[idx], cnt);
                atomicAdd(&g_sum[idx], sum);
                atomicMax(&g_max[idx], __float_as_int(mx));
            }
        }
    }
}

__global__ void finalize_kernel(float* __restrict__ out) {
    int i = blockIdx.x * blockDim.x + threadIdx.x;
    if (i >= ACC_N) return;
    int g = i / (BATCH * COUNT);
    int r = i % (BATCH * COUNT);
    int b = r / COUNT;
    int c = r % COUNT;

    float cnt = g_cnt[i];
    float sum = g_sum[i];
    float mx  = __int_as_float(g_max[i]);

    float ppv = cnt * (1.0f / (float)NPIX);
    float mpv = (cnt > 0.0f) ? (sum / cnt) : 0.0f;

    float* o = out + (size_t)b * (NGROUPS * 3 * COUNT) + g * (3 * COUNT);
    o[c]             = ppv;
    o[COUNT + c]     = mpv;
    o[2 * COUNT + c] = mx;
}

extern "C" void kernel_launch(void* const* d_in, const int* in_sizes, int n_in,
                              void* d_out, int out_size)
{
    const float* X  = (const float*)d_in[0];
    const float* w3 = (const float*)d_in[1];
    const float* b3 = (const float*)d_in[2];
    const float* w5 = (const float*)d_in[3];
    const float* b5 = (const float*)d_in[4];
    const float* w7 = (const float*)d_in[5];
    const float* b7 = (const float*)d_in[6];
    const float* w9 = (const float*)d_in[7];
    const float* b9 = (const float*)d_in[8];
    float* out = (float*)d_out;

    zero_acc_kernel<<<(ACC_N + 255) / 256, 256>>>();

    const int WTOT = NGROUPS * COUNT * 3 * KMAX * WROW;
    pack_weights_kernel<<<(WTOT + 255) / 256, 256>>>(w3, w5, w7, w9);

    dim3 grid(7, 7, BATCH * 3);   // 7x7 tiles of 32x32, batch * channel-blocks
    conv_pool_kernel<3><<<grid, 128>>>(X, b3, 0);
    conv_pool_kernel<5><<<grid, 128>>>(X, b5, 1);
    conv_pool_kernel<7><<<grid, 128>>>(X, b7, 2);
    conv_pool_kernel<9><<<grid, 128>>>(X, b9, 3);

    finalize_kernel<<<(ACC_N + 255) / 256, 256>>>(out);
}